// round 16
// baseline (speedup 1.0000x reference)
#include <cuda_runtime.h>
#include <cstdint>

// ---------------------------------------------------------------------------
// ST-LSTM persistent kernel, fp32 f32x2. Round 15 = Round 14 resubmitted
// verbatim (R15 bench was an infra/container failure, not a kernel verdict).
//  640 threads (20 warps, 5/SMSP). Warp ks owns 64 k-rows: ks 0-7 = h[s-1]
//  (waits 16 flags), 8-15 = h[s-25], 16-19 = x. 2-row load blocks.
//  red: [20][20 cols][64 b]; gate threads remapped (bg=t&63, hcg=t>>6) so
//  STS.128 and the 20-slice reduce are bank-conflict-free.
// 128 CTAs. CTA owns 4 h-cols (20 z-cols), full K=1280. SMEM 230,400 B.
// ---------------------------------------------------------------------------

#define NCTA 128
#define NTHR 640

constexpr int Bb = 64, Ii = 256, Hh = 512;
constexpr int G5H   = 2560;
constexpr int STEPS = 1600;
constexpr int HB    = Hh * Bb;     // 32768
constexpr int XB    = Ii * Bb;     // 16384
constexpr int BH    = Bb * Hh;
constexpr int NPC   = 20;          // z-cols per CTA
constexpr int KSL   = 20;          // k-slices (= warps)
constexpr int BP    = 64;          // b-stride in red
constexpr int RS2   = NPC * BP;    // 1280 floats per k-slice

constexpr int W_OFF = 0;                    // 1280*20 = 25600
constexpr int R_OFF = 25600;                // 20*1280 = 25600
constexpr int C_OFF = R_OFF + KSL * RS2;    // 25*256  = 6400
constexpr int SM_FLOATS  = C_OFF + 25 * 256;           // 57600
constexpr int SMEM_BYTES = SM_FLOATS * 4;              // 230,400 B (<=232448)

// --------------------------- device scratch --------------------------------
__device__ float    g_xT[(size_t)STEPS * XB];  // x transposed [tj][i][b]
__device__ float    g_hT[32 * HB];             // h ring [slot][n][b]
__device__ unsigned g_flags[NCTA * 8];         // per-CTA published-step counters
__device__ unsigned g_cnt = 0;                 // init barrier (one-shot, self-reset)
__device__ unsigned g_gen = 0;

// --------------------------- helpers ---------------------------------------
__device__ __forceinline__ void init_barrier() {
    __syncthreads();
    if (threadIdx.x == 0) {
        unsigned gen = *(volatile unsigned*)&g_gen;
        __threadfence();
        unsigned rank = atomicAdd(&g_cnt, 1u);
        if (rank == NCTA - 1) {
            g_cnt = 0;
            __threadfence();
            *(volatile unsigned*)&g_gen = gen + 1u;
        } else {
            while (*(volatile unsigned*)&g_gen == gen) { __nanosleep(64); }
        }
        __threadfence();
    }
    __syncthreads();
}

// warp-scoped wait: lanes 0..15 poll this warp's 16 producer flags (acquire).
__device__ __forceinline__ void warp_wait16(int prodbase, int lane, unsigned k) {
    if (lane < 16) {
        const unsigned* p = &g_flags[(prodbase + lane) * 8];
        unsigned v;
        int spins = 0;
        for (;;) {
            asm volatile("ld.acquire.gpu.global.u32 %0, [%1];" : "=r"(v) : "l"(p));
            if ((int)(v - k) >= 0) break;
            if (++spins > 16) __nanosleep(32);
        }
    }
    __syncwarp();
}

#define BAR1() asm volatile("bar.sync 1, 640;" ::: "memory")
#define BAR2() asm volatile("bar.sync 2, 640;" ::: "memory")
#define BAR3() asm volatile("bar.sync 3, 256;" ::: "memory")

__device__ __forceinline__ float fexp(float x) {
    float r;
    asm("ex2.approx.f32 %0, %1;" : "=f"(r) : "f"(x * 1.4426950408889634f));
    return r;
}
__device__ __forceinline__ float frcp(float x) {
    float r;
    asm("rcp.approx.f32 %0, %1;" : "=f"(r) : "f"(x));
    return r;
}
__device__ __forceinline__ float fsig(float x)  { return frcp(1.0f + fexp(-x)); }
__device__ __forceinline__ float ftanh(float x) { return 1.0f - 2.0f * frcp(1.0f + fexp(2.0f * x)); }

// --------------------------- kernel ----------------------------------------
__global__ void __launch_bounds__(NTHR, 1)
stlstm_kernel(const float* __restrict__ x,
              const float* __restrict__ Wx,
              const float* __restrict__ Whs,
              const float* __restrict__ Wht,
              const float* __restrict__ bias,
              float* __restrict__ out)
{
    extern __shared__ float sm[];
    float* W_s = sm + W_OFF;    // [1280][20]
    float* red = sm + R_OFF;    // [20][20 cols][64 b]
    float* c_s = sm + C_OFF;    // [25][256]

    const int t   = threadIdx.x;
    const int cta = blockIdx.x;
    const int nt  = cta;

    // -------- pre-barrier init: flags, x transpose, ring zero, weights ------
    if (t == 0) *(volatile unsigned*)&g_flags[cta * 8] = 0u;
    {
        float* tmp = red;                      // 25600 floats >= 64*257
        for (int tj = cta; tj < STEPS; tj += NCTA) {
            const float* xsrc = x + (size_t)tj * (Bb * Ii);
            for (int idx = t; idx < Bb * Ii; idx += NTHR) {
                int bb = idx >> 8, ii = idx & 255;
                tmp[bb * 257 + ii] = xsrc[idx];
            }
            __syncthreads();
            float* xdst = g_xT + (size_t)tj * XB;
            for (int idx = t; idx < Bb * Ii; idx += NTHR) {
                int ii = idx >> 6, bb = idx & 63;
                xdst[idx] = tmp[bb * 257 + ii];
            }
            __syncthreads();
        }
    }
    {   // zero h-ring slots 7..31 (all early reads land there)
        float* z = g_hT + 7 * HB;
        for (int idx = cta * NTHR + t; idx < 25 * HB; idx += NCTA * NTHR) z[idx] = 0.0f;
    }
    for (int idx = t; idx < 25 * 256; idx += NTHR) c_s[idx] = 0.0f;

    for (int idx = t; idx < 1280 * NPC; idx += NTHR) {
        int k = idx / NPC, c = idx % NPC;
        int g = c >> 2, hc = c & 3;
        int col = g * Hh + nt * 4 + hc;
        float w;
        if (k < Hh)            w = Whs[(size_t)k * G5H + col];
        else if (k < 2 * Hh)   w = Wht[(size_t)(k - Hh) * G5H + col];
        else                   w = Wx [(size_t)(k - 2 * Hh) * G5H + col];
        W_s[idx] = w;
    }

    // gate-phase identity (remapped): bg = t&63, hcg = t>>6  (t < 256)
    const int bg  = t & 63;
    const int hcg = (t >> 6) & 3;
    float ba[5];
    #pragma unroll
    for (int g = 0; g < 5; ++g) ba[g] = bias[g * Hh + nt * 4 + hcg];

    init_barrier();   // x ready, rings zeroed, flags zeroed everywhere

    // GEMM mapping: thread = (ng, mg, ks); ks warp-uniform, 20 warps.
    const int ng   = t & 1;
    const int mg   = (t >> 1) & 15;
    const int ks   = t >> 5;             // 0..19
    const int lane = t & 31;
    const int b_lo = mg * 4;
    const int ng2  = ng * 2;
    const int kWb  = ks * 64;            // W row base (uniform across classes)
    const int kcl  = (ks < 8) ? 0 : (ks < 16) ? 1 : 2;
    // per-class A offset (row base within source, in floats) + b_lo
    const int aoff = ((kcl == 0) ? (ks * 64)
                     : (kcl == 1) ? (ks * 64 - 512)
                                  : (ks * 64 - 1024)) * 64 + b_lo;
    const int prodbase = (ks & 7) * 16;  // producers for h1-warps

    unsigned long long acc[4][5];
    float4 bufA[2], bufB[2];

#define LOAD2(BUF, PA, BLK)                                                   \
    {  BUF[0] = __ldcg((const float4*)((PA) + ((BLK) * 2 + 0) * 64));         \
       BUF[1] = __ldcg((const float4*)((PA) + ((BLK) * 2 + 1) * 64)); }

#define FMA2(BUF, BLK)                                                        \
    {  _Pragma("unroll")                                                      \
       for (int u = 0; u < 2; ++u) {                                          \
           const float* wr = W_s + (kWb + (BLK) * 2 + u) * NPC + ng2;         \
           unsigned long long w0 = *(const unsigned long long*)(wr);          \
           unsigned long long w1 = *(const unsigned long long*)(wr + 4);      \
           unsigned long long w2 = *(const unsigned long long*)(wr + 8);      \
           unsigned long long w3 = *(const unsigned long long*)(wr + 12);     \
           unsigned long long w4 = *(const unsigned long long*)(wr + 16);     \
           float av[4] = {BUF[u].x, BUF[u].y, BUF[u].z, BUF[u].w};            \
           _Pragma("unroll")                                                  \
           for (int i = 0; i < 4; ++i) {                                      \
               unsigned long long aa;                                         \
               asm("mov.b64 %0, {%1, %1};" : "=l"(aa) : "f"(av[i]));          \
               asm("fma.rn.f32x2 %0, %1, %2, %0;" : "+l"(acc[i][0]) : "l"(aa), "l"(w0)); \
               asm("fma.rn.f32x2 %0, %1, %2, %0;" : "+l"(acc[i][1]) : "l"(aa), "l"(w1)); \
               asm("fma.rn.f32x2 %0, %1, %2, %0;" : "+l"(acc[i][2]) : "l"(aa), "l"(w2)); \
               asm("fma.rn.f32x2 %0, %1, %2, %0;" : "+l"(acc[i][3]) : "l"(aa), "l"(w3)); \
               asm("fma.rn.f32x2 %0, %1, %2, %0;" : "+l"(acc[i][4]) : "l"(aa), "l"(w4)); \
           } } }

#define MUL2(BUF, BLK)                                                        \
    {  _Pragma("unroll")                                                      \
       for (int u = 0; u < 2; ++u) {                                          \
           const float* wr = W_s + (kWb + (BLK) * 2 + u) * NPC + ng2;         \
           unsigned long long w0 = *(const unsigned long long*)(wr);          \
           unsigned long long w1 = *(const unsigned long long*)(wr + 4);      \
           unsigned long long w2 = *(const unsigned long long*)(wr + 8);      \
           unsigned long long w3 = *(const unsigned long long*)(wr + 12);     \
           unsigned long long w4 = *(const unsigned long long*)(wr + 16);     \
           float av[4] = {BUF[u].x, BUF[u].y, BUF[u].z, BUF[u].w};            \
           _Pragma("unroll")                                                  \
           for (int i = 0; i < 4; ++i) {                                      \
               unsigned long long aa;                                         \
               asm("mov.b64 %0, {%1, %1};" : "=l"(aa) : "f"(av[i]));          \
               if (u == 0) {                                                  \
                   asm("mul.rn.f32x2 %0, %1, %2;" : "=l"(acc[i][0]) : "l"(aa), "l"(w0)); \
                   asm("mul.rn.f32x2 %0, %1, %2;" : "=l"(acc[i][1]) : "l"(aa), "l"(w1)); \
                   asm("mul.rn.f32x2 %0, %1, %2;" : "=l"(acc[i][2]) : "l"(aa), "l"(w2)); \
                   asm("mul.rn.f32x2 %0, %1, %2;" : "=l"(acc[i][3]) : "l"(aa), "l"(w3)); \
                   asm("mul.rn.f32x2 %0, %1, %2;" : "=l"(acc[i][4]) : "l"(aa), "l"(w4)); \
               } else {                                                       \
                   asm("fma.rn.f32x2 %0, %1, %2, %0;" : "+l"(acc[i][0]) : "l"(aa), "l"(w0)); \
                   asm("fma.rn.f32x2 %0, %1, %2, %0;" : "+l"(acc[i][1]) : "l"(aa), "l"(w1)); \
                   asm("fma.rn.f32x2 %0, %1, %2, %0;" : "+l"(acc[i][2]) : "l"(aa), "l"(w2)); \
                   asm("fma.rn.f32x2 %0, %1, %2, %0;" : "+l"(acc[i][3]) : "l"(aa), "l"(w3)); \
                   asm("fma.rn.f32x2 %0, %1, %2, %0;" : "+l"(acc[i][4]) : "l"(aa), "l"(w4)); \
               } } } }

    // ---------------- main sequential loop ----------------------------------
    for (int step = 0; step < STEPS; ++step) {

        // ---- class-dependent source base; h1-warps wait first ----
        const float* src;
        if (kcl == 0) {
            if (step > 0) warp_wait16(prodbase, lane, (unsigned)step);
            src = g_hT + ((step - 1) & 31) * HB + aoff;
        } else if (kcl == 1) {
            src = g_hT + ((step - 25) & 31) * HB + aoff;
        } else {
            src = g_xT + (size_t)step * XB + aoff;
        }

        // ---- GEMM: 64 rows as 32 two-row blocks, double-buffered ----
        LOAD2(bufA, src, 0)
        LOAD2(bufB, src, 1)
        MUL2(bufA, 0)
        #pragma unroll 1
        for (int blk = 2; blk < 32; blk += 2) {
            LOAD2(bufA, src, blk)
            FMA2(bufB, blk - 1)
            LOAD2(bufB, src, blk + 1)
            FMA2(bufA, blk)
        }
        FMA2(bufB, 31)

        BAR1();   // gates(step-1) done reading red

        // ---- store partials: [ks][col][b], STS.128, conflict-free ----
        {
            float* rk = red + ks * RS2 + b_lo;
            #pragma unroll
            for (int g = 0; g < 5; ++g) {
                const float2* a0 = (const float2*)&acc[0][g];
                const float2* a1 = (const float2*)&acc[1][g];
                const float2* a2 = (const float2*)&acc[2][g];
                const float2* a3 = (const float2*)&acc[3][g];
                *(float4*)(rk + (g * 4 + ng2 + 0) * BP) =
                    make_float4(a0->x, a1->x, a2->x, a3->x);
                *(float4*)(rk + (g * 4 + ng2 + 1) * BP) =
                    make_float4(a0->y, a1->y, a2->y, a3->y);
            }
        }

        BAR2();   // all partials visible

        if (t < 256) {
            // ---- reduce 20 k-slices + gates; (bg, hcg) remapped mapping ----
            float z[5];
            #pragma unroll
            for (int g = 0; g < 5; ++g) {
                float s = ba[g];
                const float* rp = red + (g * 4 + hcg) * BP + bg;
                #pragma unroll
                for (int q = 0; q < KSL; ++q) s += rp[q * RS2];
                z[g] = s;
            }
            float cs = c_s[((step + 24) % 25) * 256 + t];
            float ct = c_s[(step % 25) * 256 + t];
            float cc = fsig(z[0]) * ftanh(z[3]) + fsig(z[1]) * cs + fsig(z[2]) * ct;
            float hv = fsig(z[4]) * ftanh(cc);

            // publish-critical store FIRST (contiguous: 32 b per warp per n)
            int n = nt * 4 + hcg;
            g_hT[(step & 31) * HB + n * 64 + bg] = hv;

            BAR3();   // all 256 h stores done
            if (t == 0) {
                unsigned k1 = (unsigned)(step + 1);
                asm volatile("st.release.gpu.global.u32 [%0], %1;"
                             :: "l"(&g_flags[cta * 8]), "r"(k1) : "memory");
            }

            // off-critical-path stores AFTER publish
            c_s[(step % 25) * 256 + t] = cc;
            out[(size_t)step * BH + bg * Hh + n] = hv;
        }
        // other warps: straight into step+1 (h25/x warps have no wait)
    }
#undef LOAD2
#undef FMA2
#undef MUL2
}

// --------------------------- launch ----------------------------------------
extern "C" void kernel_launch(void* const* d_in, const int* in_sizes, int n_in,
                              void* d_out, int out_size)
{
    const float* x    = (const float*)d_in[0];
    const float* Wx   = (const float*)d_in[1];
    const float* Whs  = (const float*)d_in[2];
    const float* Wht  = (const float*)d_in[3];
    const float* bias = (const float*)d_in[4];
    float*       out  = (float*)d_out;

    cudaFuncSetAttribute(stlstm_kernel,
                         cudaFuncAttributeMaxDynamicSharedMemorySize, SMEM_BYTES);
    stlstm_kernel<<<NCTA, NTHR, SMEM_BYTES>>>(x, Wx, Whs, Wht, bias, out);
}

// round 17
// speedup vs baseline: 1.1465x; 1.1465x over previous
#include <cuda_runtime.h>
#include <cstdint>

// ---------------------------------------------------------------------------
// ST-LSTM persistent kernel, fp32 f32x2. Round 16 = R13 (best) +
//  x-blocks moved into the post-wait window: x blk0/1 loads issued PRE-wait
//  (land during the flag RT), x-FMAs interleaved with h1-load issue so the
//  synchronized post-wait restart stall is covered. Rolling c-ring indices.
// Symmetric warps (512 thr), 8-flag per-warp wait, conflict-free red STS.128,
// pre-BAR2 prefetch of next step's h25 block 0.
// 128 CTAs. CTA owns 4 h-cols (20 z-cols), full K=1280. SMEM 215,040 B.
// ---------------------------------------------------------------------------

#define NCTA 128
#define NTHR 512

constexpr int Bb = 64, Ii = 256, Hh = 512;
constexpr int G5H   = 2560;
constexpr int STEPS = 1600;
constexpr int HB    = Hh * Bb;     // 32768
constexpr int XB    = Ii * Bb;     // 16384
constexpr int BH    = Bb * Hh;
constexpr int NPC   = 20;          // z-cols per CTA
constexpr int KSL   = 16;          // k-slices (= warps)
constexpr int BP    = 68;          // b-stride in red (64 + 4 pad)
constexpr int RS2   = NPC * BP;    // 1360 floats per k-slice

constexpr int W_OFF = 0;                    // 1280*20 = 25600
constexpr int R_OFF = 25600;                // 16*1360 = 21760
constexpr int C_OFF = R_OFF + KSL * RS2;    // 25*256  = 6400
constexpr int SM_FLOATS  = C_OFF + 25 * 256;           // 53760
constexpr int SMEM_BYTES = SM_FLOATS * 4;              // 215,040 B

// --------------------------- device scratch --------------------------------
__device__ float    g_xT[(size_t)STEPS * XB];  // x transposed [tj][i][b]
__device__ float    g_hT[32 * HB];             // h ring [slot][n][b]
__device__ unsigned g_flags[NCTA * 8];         // per-CTA published-step counters
__device__ unsigned g_cnt = 0;                 // init barrier (one-shot, self-reset)
__device__ unsigned g_gen = 0;

// --------------------------- helpers ---------------------------------------
__device__ __forceinline__ void init_barrier() {
    __syncthreads();
    if (threadIdx.x == 0) {
        unsigned gen = *(volatile unsigned*)&g_gen;
        __threadfence();
        unsigned rank = atomicAdd(&g_cnt, 1u);
        if (rank == NCTA - 1) {
            g_cnt = 0;
            __threadfence();
            *(volatile unsigned*)&g_gen = gen + 1u;
        } else {
            while (*(volatile unsigned*)&g_gen == gen) { __nanosleep(64); }
        }
        __threadfence();
    }
    __syncthreads();
}

// warp-scoped wait: lanes 0..7 poll this warp's 8 producer flags (acquire).
__device__ __forceinline__ void warp_wait8(int prodbase, int lane, unsigned k) {
    if (lane < 8) {
        const unsigned* p = &g_flags[(prodbase + lane) * 8];
        unsigned v;
        int spins = 0;
        for (;;) {
            asm volatile("ld.acquire.gpu.global.u32 %0, [%1];" : "=r"(v) : "l"(p));
            if ((int)(v - k) >= 0) break;
            if (++spins > 16) __nanosleep(32);
        }
    }
    __syncwarp();
}

#define BAR1() asm volatile("bar.sync 1, 512;" ::: "memory")
#define BAR2() asm volatile("bar.sync 2, 512;" ::: "memory")
#define BAR3() asm volatile("bar.sync 3, 256;" ::: "memory")

__device__ __forceinline__ float fexp(float x) {
    float r;
    asm("ex2.approx.f32 %0, %1;" : "=f"(r) : "f"(x * 1.4426950408889634f));
    return r;
}
__device__ __forceinline__ float frcp(float x) {
    float r;
    asm("rcp.approx.f32 %0, %1;" : "=f"(r) : "f"(x));
    return r;
}
__device__ __forceinline__ float fsig(float x)  { return frcp(1.0f + fexp(-x)); }
__device__ __forceinline__ float ftanh(float x) { return 1.0f - 2.0f * frcp(1.0f + fexp(2.0f * x)); }

// --------------------------- kernel ----------------------------------------
__global__ void __launch_bounds__(NTHR, 1)
stlstm_kernel(const float* __restrict__ x,
              const float* __restrict__ Wx,
              const float* __restrict__ Whs,
              const float* __restrict__ Wht,
              const float* __restrict__ bias,
              float* __restrict__ out)
{
    extern __shared__ float sm[];
    float* W_s = sm + W_OFF;
    float* red = sm + R_OFF;    // [16][20 cols][68 b]
    float* c_s = sm + C_OFF;

    const int t   = threadIdx.x;
    const int cta = blockIdx.x;
    const int nt  = cta;

    // -------- pre-barrier init: flags, x transpose, ring zero, weights ------
    if (t == 0) *(volatile unsigned*)&g_flags[cta * 8] = 0u;
    {
        float* tmp = red;                      // 21760 floats >= 64*257
        for (int tj = cta; tj < STEPS; tj += NCTA) {
            const float* xsrc = x + (size_t)tj * (Bb * Ii);
            for (int idx = t; idx < Bb * Ii; idx += NTHR) {
                int bb = idx >> 8, ii = idx & 255;
                tmp[bb * 257 + ii] = xsrc[idx];
            }
            __syncthreads();
            float* xdst = g_xT + (size_t)tj * XB;
            for (int idx = t; idx < Bb * Ii; idx += NTHR) {
                int ii = idx >> 6, bb = idx & 63;
                xdst[idx] = tmp[bb * 257 + ii];
            }
            __syncthreads();
        }
    }
    {   // zero h-ring slots 7..31 (all early reads land there)
        float* z = g_hT + 7 * HB;
        for (int idx = cta * NTHR + t; idx < 25 * HB; idx += NCTA * NTHR) z[idx] = 0.0f;
    }
    for (int idx = t; idx < 25 * 256; idx += NTHR) c_s[idx] = 0.0f;

    for (int idx = t; idx < 1280 * NPC; idx += NTHR) {
        int k = idx / NPC, c = idx % NPC;
        int g = c >> 2, hc = c & 3;
        int col = g * Hh + nt * 4 + hc;
        float w;
        if (k < Hh)            w = Whs[(size_t)k * G5H + col];
        else if (k < 2 * Hh)   w = Wht[(size_t)(k - Hh) * G5H + col];
        else                   w = Wx [(size_t)(k - 2 * Hh) * G5H + col];
        W_s[idx] = w;
    }

    float ba[5];
    {
        int hc = t & 3;
        #pragma unroll
        for (int g = 0; g < 5; ++g) ba[g] = bias[g * Hh + nt * 4 + hc];
    }

    init_barrier();   // x ready, rings zeroed, flags zeroed everywhere

    // GEMM mapping: thread = (ng, mg, ks); ks warp-uniform.
    const int ng    = t & 1;
    const int mg    = (t >> 1) & 15;
    const int ks    = t >> 5;
    const int lane  = t & 31;
    const int b_lo  = mg * 4;
    const int ng2   = ng * 2;
    const int kh1W  = ks * 32;           // W row base, h1 part
    const int kh25W = 512 + ks * 32;     // W row base, h25 part
    const int kxW   = 1024 + ks * 16;    // W row base, x part

    const int prodbase = ks * 8;         // 8 producer CTAs (h-cols ks*32..+31)

    const int bg  = t >> 2;              // gate phase (t < 256)
    const int hcg = t & 3;

    // rolling c-ring indices (replace %25 in the tail)
    int cring_cur = 0;                   // step % 25
    int cring_prev = 24;                 // (step+24) % 25

    unsigned long long acc[4][5];
    float4 bufA[4], bufB[4];

#define LOADBLK(BUF, PA, BLK)                                                 \
    {  _Pragma("unroll")                                                      \
       for (int u = 0; u < 4; ++u)                                            \
           BUF[u] = __ldcg((const float4*)((PA) + ((BLK) * 4 + u) * 64));     \
    }

#define FMABLK(BUF, KWB, BLK)                                                 \
    {  _Pragma("unroll")                                                      \
       for (int u = 0; u < 4; ++u) {                                          \
           const float* wr = W_s + ((KWB) + (BLK) * 4 + u) * NPC + ng2;       \
           unsigned long long w0 = *(const unsigned long long*)(wr);          \
           unsigned long long w1 = *(const unsigned long long*)(wr + 4);      \
           unsigned long long w2 = *(const unsigned long long*)(wr + 8);      \
           unsigned long long w3 = *(const unsigned long long*)(wr + 12);     \
           unsigned long long w4 = *(const unsigned long long*)(wr + 16);     \
           float av[4] = {BUF[u].x, BUF[u].y, BUF[u].z, BUF[u].w};            \
           _Pragma("unroll")                                                  \
           for (int i = 0; i < 4; ++i) {                                      \
               unsigned long long aa;                                         \
               asm("mov.b64 %0, {%1, %1};" : "=l"(aa) : "f"(av[i]));          \
               asm("fma.rn.f32x2 %0, %1, %2, %0;" : "+l"(acc[i][0]) : "l"(aa), "l"(w0)); \
               asm("fma.rn.f32x2 %0, %1, %2, %0;" : "+l"(acc[i][1]) : "l"(aa), "l"(w1)); \
               asm("fma.rn.f32x2 %0, %1, %2, %0;" : "+l"(acc[i][2]) : "l"(aa), "l"(w2)); \
               asm("fma.rn.f32x2 %0, %1, %2, %0;" : "+l"(acc[i][3]) : "l"(aa), "l"(w3)); \
               asm("fma.rn.f32x2 %0, %1, %2, %0;" : "+l"(acc[i][4]) : "l"(aa), "l"(w4)); \
           } } }

#define MULBLK(BUF, KWB, BLK)                                                 \
    {  _Pragma("unroll")                                                      \
       for (int u = 0; u < 4; ++u) {                                          \
           const float* wr = W_s + ((KWB) + (BLK) * 4 + u) * NPC + ng2;       \
           unsigned long long w0 = *(const unsigned long long*)(wr);          \
           unsigned long long w1 = *(const unsigned long long*)(wr + 4);      \
           unsigned long long w2 = *(const unsigned long long*)(wr + 8);      \
           unsigned long long w3 = *(const unsigned long long*)(wr + 12);     \
           unsigned long long w4 = *(const unsigned long long*)(wr + 16);     \
           float av[4] = {BUF[u].x, BUF[u].y, BUF[u].z, BUF[u].w};            \
           _Pragma("unroll")                                                  \
           for (int i = 0; i < 4; ++i) {                                      \
               unsigned long long aa;                                         \
               asm("mov.b64 %0, {%1, %1};" : "=l"(aa) : "f"(av[i]));          \
               if (u == 0) {                                                  \
                   asm("mul.rn.f32x2 %0, %1, %2;" : "=l"(acc[i][0]) : "l"(aa), "l"(w0)); \
                   asm("mul.rn.f32x2 %0, %1, %2;" : "=l"(acc[i][1]) : "l"(aa), "l"(w1)); \
                   asm("mul.rn.f32x2 %0, %1, %2;" : "=l"(acc[i][2]) : "l"(aa), "l"(w2)); \
                   asm("mul.rn.f32x2 %0, %1, %2;" : "=l"(acc[i][3]) : "l"(aa), "l"(w3)); \
                   asm("mul.rn.f32x2 %0, %1, %2;" : "=l"(acc[i][4]) : "l"(aa), "l"(w4)); \
               } else {                                                       \
                   asm("fma.rn.f32x2 %0, %1, %2, %0;" : "+l"(acc[i][0]) : "l"(aa), "l"(w0)); \
                   asm("fma.rn.f32x2 %0, %1, %2, %0;" : "+l"(acc[i][1]) : "l"(aa), "l"(w1)); \
                   asm("fma.rn.f32x2 %0, %1, %2, %0;" : "+l"(acc[i][2]) : "l"(aa), "l"(w2)); \
                   asm("fma.rn.f32x2 %0, %1, %2, %0;" : "+l"(acc[i][3]) : "l"(aa), "l"(w3)); \
                   asm("fma.rn.f32x2 %0, %1, %2, %0;" : "+l"(acc[i][4]) : "l"(aa), "l"(w4)); \
               } } } }

    // prologue: prefetch h25 block 0 of step 0 (slot 7 zeroed)
    {
        const float* pH0 = g_hT + ((0 - 25) & 31) * HB + kh1W * 64 + b_lo;
        LOADBLK(bufA, pH0, 0)
    }

    // ---------------- main sequential loop ----------------------------------
    for (int step = 0; step < STEPS; ++step) {

        const float* pX = g_xT + (size_t)step * XB + (ks * 16) * 64 + b_lo;

        // ===== phase A (independent): h[s-25] 8 blocks (blk0 prefetched) ====
        {
            const float* pH = g_hT + ((step - 25) & 31) * HB + kh1W * 64 + b_lo;
            LOADBLK(bufB, pH, 1)
            MULBLK(bufA, kh25W, 0)
            #pragma unroll 1
            for (int blk = 1; blk < 7; blk += 2) {
                LOADBLK(bufA, pH, blk + 1)
                FMABLK(bufB, kh25W, blk)
                LOADBLK(bufB, pH, blk + 2)
                FMABLK(bufA, kh25W, blk + 1)
            }
            FMABLK(bufB, kh25W, 7)
        }

        // ===== pre-wait: issue x blk0/1 loads (fly during the flag RT) =====
        LOADBLK(bufA, pX, 0)
        LOADBLK(bufB, pX, 1)

        // ===== per-warp wait (8 flags; steady state: already set) =====
        if (step > 0) warp_wait8(prodbase, lane, (unsigned)step);

        // ===== post-wait: x-FMAs interleaved with h1-load issue =====
        {
            const float* pH = g_hT + ((step - 1) & 31) * HB + kh1W * 64 + b_lo;
            FMABLK(bufA, kxW, 0)          // x0 (landed during wait)
            LOADBLK(bufA, pH, 0)          // h0 in flight
            FMABLK(bufB, kxW, 1)          // x1
            LOADBLK(bufB, pX, 2)          // x2 in flight
            FMABLK(bufA, kh1W, 0)         // h0
            LOADBLK(bufA, pX, 3)          // x3 in flight
            FMABLK(bufB, kxW, 2)          // x2
            LOADBLK(bufB, pH, 1)          // h1 in flight
            FMABLK(bufA, kxW, 3)          // x3
            LOADBLK(bufA, pH, 2)          // h2 in flight
            FMABLK(bufB, kh1W, 1)         // h1
            LOADBLK(bufB, pH, 3)          // h3 in flight
            // steady double-buffer for h1 blocks 2..7
            FMABLK(bufA, kh1W, 2)
            LOADBLK(bufA, pH, 4)
            FMABLK(bufB, kh1W, 3)
            LOADBLK(bufB, pH, 5)
            FMABLK(bufA, kh1W, 4)
            LOADBLK(bufA, pH, 6)
            FMABLK(bufB, kh1W, 5)
            LOADBLK(bufB, pH, 7)
            FMABLK(bufA, kh1W, 6)
            FMABLK(bufB, kh1W, 7)
        }

        BAR1();   // gates(step-1) done reading red

        // ---- store partials: [ks][col][b], STS.128, conflict-free ----
        {
            float* rk = red + ks * RS2 + b_lo;
            #pragma unroll
            for (int g = 0; g < 5; ++g) {
                const float2* a0 = (const float2*)&acc[0][g];
                const float2* a1 = (const float2*)&acc[1][g];
                const float2* a2 = (const float2*)&acc[2][g];
                const float2* a3 = (const float2*)&acc[3][g];
                *(float4*)(rk + (g * 4 + ng2 + 0) * BP) =
                    make_float4(a0->x, a1->x, a2->x, a3->x);
                *(float4*)(rk + (g * 4 + ng2 + 1) * BP) =
                    make_float4(a0->y, a1->y, a2->y, a3->y);
            }
        }

        // ---- prefetch h25(s+1) block 0 BEFORE the barrier ----
        {
            const float* pHn = g_hT + ((step - 24) & 31) * HB + kh1W * 64 + b_lo;
            LOADBLK(bufA, pHn, 0)
        }

        BAR2();   // all partials visible

        if (ks < 8) {
            // ---- reduce 16 k-slices + gates (threads 0..255) ----
            float z[5];
            #pragma unroll
            for (int g = 0; g < 5; ++g) {
                float s = ba[g];
                const float* rp = red + (g * 4 + hcg) * BP + bg;
                #pragma unroll
                for (int q = 0; q < KSL; ++q) s += rp[q * RS2];
                z[g] = s;
            }
            float cs = c_s[cring_prev * 256 + t];
            float ct = c_s[cring_cur * 256 + t];
            float cc = fsig(z[0]) * ftanh(z[3]) + fsig(z[1]) * cs + fsig(z[2]) * ct;
            float hv = fsig(z[4]) * ftanh(cc);

            // publish-critical store FIRST
            int n = nt * 4 + hcg;
            g_hT[(step & 31) * HB + n * 64 + bg] = hv;

            BAR3();   // all 256 h stores done
            if (t == 0) {
                unsigned k1 = (unsigned)(step + 1);
                asm volatile("st.release.gpu.global.u32 [%0], %1;"
                             :: "l"(&g_flags[cta * 8]), "r"(k1) : "memory");
            }

            // off-critical-path stores AFTER publish
            c_s[cring_cur * 256 + t] = cc;
            out[(size_t)step * BH + bg * Hh + n] = hv;
        }
        // advance rolling c-ring indices (all threads, cheap)
        cring_prev = cring_cur;
        cring_cur  = (cring_cur == 24) ? 0 : cring_cur + 1;
        // warps 8-15: straight into step+1's phase A (bufA already in flight)
    }
#undef LOADBLK
#undef FMABLK
#undef MULBLK
}

// --------------------------- launch ----------------------------------------
extern "C" void kernel_launch(void* const* d_in, const int* in_sizes, int n_in,
                              void* d_out, int out_size)
{
    const float* x    = (const float*)d_in[0];
    const float* Wx   = (const float*)d_in[1];
    const float* Whs  = (const float*)d_in[2];
    const float* Wht  = (const float*)d_in[3];
    const float* bias = (const float*)d_in[4];
    float*       out  = (float*)d_out;

    cudaFuncSetAttribute(stlstm_kernel,
                         cudaFuncAttributeMaxDynamicSharedMemorySize, SMEM_BYTES);
    stlstm_kernel<<<NCTA, NTHR, SMEM_BYTES>>>(x, Wx, Whs, Wht, bias, out);
}